// round 13
// baseline (speedup 1.0000x reference)
#include <cuda_runtime.h>
#include <cstdint>

// CRF loss: mean_b( logZ_b - gold_b )
// Forward recurrence in LINEAR space; lane = state.
//   e_t[n] = (expM @ e_{t-1})[n] * exp(emit_t[n]) * 2^{-k},  off += k
// KEY: the chain is LATENCY-bound (~200cyc/step at <40% issue for every
// variant tried), so each warp interleaves TWO independent sequences
// (b and b+B/2). Chain B's instructions issue inside chain A's stall
// shadow -> ~2 steps per ~200cyc round. M[30] registers shared (same
// transition matrix). Inactive steps predicated (SEL), body branch-free.
// Renorm every 4 steps via shfl of e[0] (exact via integer off).
// Gold score computed by warp 1 of the same block. Mean fused at the end.

#define KSTATES   32
#define START_IDX 30
#define STOP_IDX  31
#define FULLMASK  0xffffffffu
#define LN2       0.6931471805599453f

__device__ float    g_fwd[4096];
__device__ float    g_gold[4096];
__device__ unsigned g_count;          // zero-init; reset by last block

// s[lane] = sum_{p=0..29} M[p] * e[p]  (e broadcast via shfl).
// p=30 (e[START]=0 for t>=1) and p=31 (column STOP = 0) drop out.
__device__ __forceinline__ float crf_dot30(const float* __restrict__ M, float e)
{
    float a0 = 0.f, a1 = 0.f, a2 = 0.f, a3 = 0.f;
#pragma unroll
    for (int p = 0; p < 28; p += 4) {
        a0 = fmaf(M[p    ], __shfl_sync(FULLMASK, e, p    ), a0);
        a1 = fmaf(M[p + 1], __shfl_sync(FULLMASK, e, p + 1), a1);
        a2 = fmaf(M[p + 2], __shfl_sync(FULLMASK, e, p + 2), a2);
        a3 = fmaf(M[p + 3], __shfl_sync(FULLMASK, e, p + 3), a3);
    }
    a0 = fmaf(M[28], __shfl_sync(FULLMASK, e, 28), a0);
    a1 = fmaf(M[29], __shfl_sync(FULLMASK, e, 29), a1);
    return (a0 + a1) + (a2 + a3);
}

// 2^-k from e[0]'s exponent; k accumulated into off only when act.
__device__ __forceinline__ float crf_renorm(float e, int& off, bool act)
{
    float c  = __shfl_sync(FULLMASK, e, 0);
    int   ie = (int)((__float_as_uint(c) >> 23) & 0xFF);
    ie = (ie == 0) ? 127 : ie;
    off += act ? (ie - 127) : 0;
    return act ? __uint_as_float((unsigned)(254 - ie) << 23) : 1.0f;
}

__global__ void __launch_bounds__(64)
crf_fused_kernel(const float* __restrict__ feats,
                 const float* __restrict__ trans,
                 const int*   __restrict__ tags,
                 const int*   __restrict__ lens,
                 float* __restrict__ out,
                 int B, int T)
{
    const int tid  = threadIdx.x;
    const int wid  = tid >> 5;
    const int lane = tid & 31;

    const int bA = blockIdx.x;
    const int bB = blockIdx.x + (B >> 1);

    if (wid == 0) {
        // ============ FORWARD: two interleaved chains ============
        float M[30];
#pragma unroll
        for (int p = 0; p < 30; p++)
            M[p] = __expf(trans[lane * KSTATES + p]);     // exp(-10000) -> 0

        const int lenA = lens[bA], lenB = lens[bB];
        const float* fA = feats + (size_t)bA * T * KSTATES + lane;
        const float* fB = feats + (size_t)bB * T * KSTATES + lane;

        // t = 0 peeled: e[n] = exp(trans[n][START] + emit0[n])
        const float tS = trans[lane * KSTATES + START_IDX];
        float eA = __expf(tS + fA[0]);
        float eB = __expf(tS + fB[0]);
        int offA = 0, offB = 0;

        const int stepsA = lenA - 1, stepsB = lenB - 1;
        const int steps  = (stepsA > stepsB) ? stepsA : stepsB;

        float fbufA[8], fbufB[8];
#pragma unroll
        for (int i = 0; i < 8; i++) {
            fbufA[i] = (1 + i < lenA) ? fA[(size_t)(1 + i) * KSTATES] : 0.0f;
            fbufB[i] = (1 + i < lenB) ? fB[(size_t)(1 + i) * KSTATES] : 0.0f;
        }

        const int s8 = steps & ~7;
        for (int t0 = 0; t0 < s8; t0 += 8) {
#pragma unroll
            for (int j = 0; j < 8; j++) {                // branch-free body
                const int  s    = t0 + j;
                const bool actA = s < stepsA;
                const bool actB = s < stepsB;
                float hA = __expf(fbufA[j]);             // MUFU, off-path
                float hB = __expf(fbufB[j]);
                if ((j & 3) == 0) {                      // renorm every 4 steps
                    hA *= crf_renorm(eA, offA, actA);
                    hB *= crf_renorm(eB, offB, actB);
                }
                float sA = crf_dot30(M, eA);             // two independent
                float sB = crf_dot30(M, eB);             // latency chains
                eA = actA ? sA * hA : eA;                // predicated freeze
                eB = actB ? sB * hB : eB;
                int tt = 9 + t0 + j;                     // refill slot j
                fbufA[j] = (tt < lenA) ? fA[(size_t)tt * KSTATES] : 0.0f;
                fbufB[j] = (tt < lenB) ? fB[(size_t)tt * KSTATES] : 0.0f;
            }
        }
        for (int s = s8; s < steps; s++) {               // <=7 step tail
            const int  i    = s - s8;
            const bool actA = s < stepsA;
            const bool actB = s < stepsB;
            float hA = __expf(fbufA[i]) * crf_renorm(eA, offA, actA);
            float hB = __expf(fbufB[i]) * crf_renorm(eB, offB, actB);
            float sA = crf_dot30(M, eA);
            float sB = crf_dot30(M, eB);
            eA = actA ? sA * hA : eA;
            eB = actB ? sB * hB : eB;
        }

        // forward_score = off*ln2 + log( (expM @ e)[STOP] ); renorm is in off
        float sfA = crf_dot30(M, eA);                    // lane 31 = STOP row
        float sfB = crf_dot30(M, eB);
        float stopA = __shfl_sync(FULLMASK, sfA, STOP_IDX);
        float stopB = __shfl_sync(FULLMASK, sfB, STOP_IDX);
        if (lane == 0) {
            g_fwd[bA] = (float)offA * LN2 + __logf(stopA);
            g_fwd[bB] = (float)offB * LN2 + __logf(stopB);
        }
    } else {
        // ============ GOLD: both batches, embarrassingly parallel ============
#pragma unroll
        for (int c = 0; c < 2; c++) {
            const int bb = c ? bB : bA;
            const int* tb = tags + (size_t)bb * T;
            const float* fbase = feats + (size_t)bb * T * KSTATES;
            const int len = lens[bb];
            float g = 0.0f;
            for (int t = lane; t < len; t += 32) {
                int tg    = tb[t];
                int tprev = (t == 0) ? START_IDX : tb[t - 1];
                g += fbase[(size_t)t * KSTATES + tg] + trans[tg * KSTATES + tprev];
            }
#pragma unroll
            for (int d = 16; d; d >>= 1)
                g += __shfl_xor_sync(FULLMASK, g, d);
            if (lane == 0)
                g_gold[bb] = g + trans[STOP_IDX * KSTATES + tb[len - 1]];
        }
    }

    // ---- fused mean: last block reduces (fwd - gold) deterministically ----
    __shared__ unsigned sh_last;
    __syncthreads();
    if (tid == 0) {
        __threadfence();
        unsigned old = atomicAdd(&g_count, 1u);
        sh_last = (old == gridDim.x - 1) ? 1u : 0u;
    }
    __syncthreads();
    if (sh_last && wid == 0) {
        __threadfence();
        float v = 0.0f;
        for (int i = lane; i < B; i += 32)       // fixed order -> deterministic
            v += g_fwd[i] - g_gold[i];
#pragma unroll
        for (int d = 16; d; d >>= 1)
            v += __shfl_xor_sync(FULLMASK, v, d);
        if (lane == 0) {
            out[0] = v / (float)B;
            g_count = 0;                         // reset for next graph replay
        }
    }
}

extern "C" void kernel_launch(void* const* d_in, const int* in_sizes, int n_in,
                              void* d_out, int out_size)
{
    const float* feats = (const float*)d_in[0];   // [B,T,K] f32
    const float* trans = (const float*)d_in[1];   // [K,K]   f32
    const int*   tags  = (const int*)  d_in[2];   // [B,T]   i32
    const int*   lens  = (const int*)  d_in[3];   // [B]     i32

    int B = in_sizes[3];
    int T = in_sizes[2] / B;

    crf_fused_kernel<<<B / 2, 64>>>(feats, trans, tags, lens, (float*)d_out, B, T);
}

// round 15
// speedup vs baseline: 2.1682x; 2.1682x over previous
#include <cuda_runtime.h>
#include <cstdint>

// CRF loss: mean_b( logZ_b - gold_b )
// Forward recurrence in LINEAR space, one warp per batch, lane = state.
//   e_t[n] = (expM @ e_{t-1})[n] * exp(emit_t[n]) * 2^{-k},  off += k
// HYBRID exchange per step (the all-gather is split across both HW paths,
// which run CONCURRENTLY):
//   e[0..15]  -> 16 SHFL broadcasts   (shuffle unit: issue ~64, lat 26)
//   e[16..31] -> 2x LDS.128 from smem (LSU: issue ~4, store->load ~75)
// Only lanes 16..31 store to smem (predicated). Renorm reuses the p=0
// broadcast -> zero extra cost; exact via integer 'off'. Structural zeros
// (M column STOP = 0, e[START] = 0 for t>=1) make p=30,31 safe to include.
// Gold score in a separate parallel kernel; mean fused via last-block reduce.

#define KSTATES   32
#define START_IDX 30
#define STOP_IDX  31
#define FULLMASK  0xffffffffu
#define LN2       0.6931471805599453f

__device__ float    g_fwd[4096];
__device__ float    g_gold[4096];
__device__ unsigned g_count;          // zero-init; reset by last block

// One hybrid dot: s[lane] = sum_{p=0..31} M[p]*e[p]
// (p=31 term is 0 via M, p=30 term is 0 via e).
// Msc: scalar expM[lane][0..15]; Mp2: packed expM[lane][16..31] as 8 f32x2.
// b0_out: broadcast copy of e[0] (for the renorm).
__device__ __forceinline__ float crf_dot_hybrid(const float* __restrict__ Msc,
                                                const unsigned long long* __restrict__ Mp2,
                                                unsigned eaddr, float e,
                                                float& b0_out)
{
    // --- shuffle half: p = 0..15 (16 independent broadcasts) ---
    float bb[16];
#pragma unroll
    for (int p = 0; p < 16; p++)
        bb[p] = __shfl_sync(FULLMASK, e, p);
    b0_out = bb[0];

    // --- smem half: p = 16..31 (2x LDS.128, reads last step's stores) ---
    unsigned long long ev[4];
    asm volatile("ld.shared.v2.u64 {%0,%1}, [%2];"
                 : "=l"(ev[0]), "=l"(ev[1]) : "r"(eaddr + 64u));
    asm volatile("ld.shared.v2.u64 {%0,%1}, [%2];"
                 : "=l"(ev[2]), "=l"(ev[3]) : "r"(eaddr + 80u));

    // scalar chains (4 deep x 4)
    float a0 = 0.f, a1 = 0.f, a2 = 0.f, a3 = 0.f;
#pragma unroll
    for (int p = 0; p < 16; p += 4) {
        a0 = fmaf(Msc[p    ], bb[p    ], a0);
        a1 = fmaf(Msc[p + 1], bb[p + 1], a1);
        a2 = fmaf(Msc[p + 2], bb[p + 2], a2);
        a3 = fmaf(Msc[p + 3], bb[p + 3], a3);
    }
    // packed chains (2 deep x 4)
    unsigned long long q0 = 0ull, q1 = 0ull, q2 = 0ull, q3 = 0ull;
    asm("fma.rn.f32x2 %0, %1, %2, %0;" : "+l"(q0) : "l"(Mp2[0]), "l"(ev[0]));
    asm("fma.rn.f32x2 %0, %1, %2, %0;" : "+l"(q1) : "l"(Mp2[1]), "l"(ev[1]));
    asm("fma.rn.f32x2 %0, %1, %2, %0;" : "+l"(q2) : "l"(Mp2[2]), "l"(ev[2]));
    asm("fma.rn.f32x2 %0, %1, %2, %0;" : "+l"(q3) : "l"(Mp2[3]), "l"(ev[3]));
    asm("fma.rn.f32x2 %0, %1, %2, %0;" : "+l"(q0) : "l"(Mp2[4]), "l"(ev[0]) );
    // NOTE: Mp2[4..7] pair with ev re-fetch? No -- ev[] covers e[16..31] in 4
    // f32x2 words; Mp2[4..7] multiply the SAME 4 words' partners. Correct
    // pairing: Mp2[q] multiplies ev[q&3]? NO. See corrected full pairing below.
    return 0.0f; // (placeholder, replaced below)
}

// ---- corrected hybrid dot (Mp2[q] pairs 1:1 with ev word q of 8 halves) ----
// e[16..31] = 16 floats = 8 f32x2 words -> need 4x ld.v2.u64 giving 8 words.
__device__ __forceinline__ float crf_dot_hybrid2(const float* __restrict__ Msc,
                                                 const unsigned long long* __restrict__ Mp2,
                                                 unsigned eaddr, float e,
                                                 float& b0_out)
{
    float bb[16];
#pragma unroll
    for (int p = 0; p < 16; p++)
        bb[p] = __shfl_sync(FULLMASK, e, p);
    b0_out = bb[0];

    unsigned long long ev[8];
    asm volatile("ld.shared.v2.u64 {%0,%1}, [%2];"
                 : "=l"(ev[0]), "=l"(ev[1]) : "r"(eaddr + 64u));
    asm volatile("ld.shared.v2.u64 {%0,%1}, [%2];"
                 : "=l"(ev[2]), "=l"(ev[3]) : "r"(eaddr + 80u));
    asm volatile("ld.shared.v2.u64 {%0,%1}, [%2];"
                 : "=l"(ev[4]), "=l"(ev[5]) : "r"(eaddr + 96u));
    asm volatile("ld.shared.v2.u64 {%0,%1}, [%2];"
                 : "=l"(ev[6]), "=l"(ev[7]) : "r"(eaddr + 112u));

    float a0 = 0.f, a1 = 0.f, a2 = 0.f, a3 = 0.f;
#pragma unroll
    for (int p = 0; p < 16; p += 4) {
        a0 = fmaf(Msc[p    ], bb[p    ], a0);
        a1 = fmaf(Msc[p + 1], bb[p + 1], a1);
        a2 = fmaf(Msc[p + 2], bb[p + 2], a2);
        a3 = fmaf(Msc[p + 3], bb[p + 3], a3);
    }
    unsigned long long q0 = 0ull, q1 = 0ull, q2 = 0ull, q3 = 0ull;
    asm("fma.rn.f32x2 %0, %1, %2, %0;" : "+l"(q0) : "l"(Mp2[0]), "l"(ev[0]));
    asm("fma.rn.f32x2 %0, %1, %2, %0;" : "+l"(q1) : "l"(Mp2[1]), "l"(ev[1]));
    asm("fma.rn.f32x2 %0, %1, %2, %0;" : "+l"(q2) : "l"(Mp2[2]), "l"(ev[2]));
    asm("fma.rn.f32x2 %0, %1, %2, %0;" : "+l"(q3) : "l"(Mp2[3]), "l"(ev[3]));
    asm("fma.rn.f32x2 %0, %1, %2, %0;" : "+l"(q0) : "l"(Mp2[4]), "l"(ev[4]));
    asm("fma.rn.f32x2 %0, %1, %2, %0;" : "+l"(q1) : "l"(Mp2[5]), "l"(ev[5]));
    asm("fma.rn.f32x2 %0, %1, %2, %0;" : "+l"(q2) : "l"(Mp2[6]), "l"(ev[6]));
    asm("fma.rn.f32x2 %0, %1, %2, %0;" : "+l"(q3) : "l"(Mp2[7]), "l"(ev[7]));

    unsigned long long s01, s23, sp;
    asm("add.rn.f32x2 %0, %1, %2;" : "=l"(s01) : "l"(q0),  "l"(q1));
    asm("add.rn.f32x2 %0, %1, %2;" : "=l"(s23) : "l"(q2),  "l"(q3));
    asm("add.rn.f32x2 %0, %1, %2;" : "=l"(sp)  : "l"(s01), "l"(s23));
    float lo, hi;
    asm("mov.b64 {%0, %1}, %2;" : "=f"(lo), "=f"(hi) : "l"(sp));

    return ((a0 + a1) + (a2 + a3)) + ((lo + hi));
}

__device__ __forceinline__ void crf_store_hi(unsigned eaddr, int lane, float e)
{
    if (lane >= 16)
        asm volatile("st.shared.f32 [%0], %1;"
                     :: "r"(eaddr + 4u * (unsigned)lane), "f"(e));
}

// 2^-k from e[0]'s bits (already broadcast); k accumulated into off.
__device__ __forceinline__ float crf_renorm_b0(float b0, int& off)
{
    int ie = (int)((__float_as_uint(b0) >> 23) & 0xFF);
    ie = (ie == 0) ? 127 : ie;
    off += ie - 127;
    return __uint_as_float((unsigned)(254 - ie) << 23);
}

__global__ void __launch_bounds__(32)
crf_forward_kernel(const float* __restrict__ feats,
                   const float* __restrict__ trans,
                   const int*   __restrict__ lens,
                   float* __restrict__ out,
                   int B, int T)
{
    __shared__ __align__(16) float sh_e[KSTATES];

    const int lane = threadIdx.x & 31;
    const int b    = blockIdx.x;
    const unsigned eaddr = (unsigned)__cvta_generic_to_shared(sh_e);

    // Scalar expM for p=0..15; packed f32x2 expM for p=16..31.
    // exp(-10000) -> exactly 0 (row START all-zero, column STOP zero).
    float Msc[16];
#pragma unroll
    for (int p = 0; p < 16; p++)
        Msc[p] = __expf(trans[lane * KSTATES + p]);
    unsigned long long Mp2[8];
#pragma unroll
    for (int q = 0; q < 8; q++) {
        float m0 = __expf(trans[lane * KSTATES + 16 + 2 * q]);
        float m1 = __expf(trans[lane * KSTATES + 16 + 2 * q + 1]);
        asm("mov.b64 %0, {%1, %2};" : "=l"(Mp2[q]) : "f"(m0), "f"(m1));
    }

    const int len = lens[b];
    const float* fb = feats + (size_t)b * T * KSTATES + lane;

    // ---- t = 0 peeled: e[n] = exp(trans[n][START] + emit0[n]) ----
    float e   = __expf(trans[lane * KSTATES + START_IDX] + fb[0]);
    int   off = 0;
    crf_store_hi(eaddr, lane, e);

    // ---- steps t = 1 .. len-1; 8-unrolled, 8-deep clamped prefetch ----
    const int steps = len - 1;
    float fbuf[8];
#pragma unroll
    for (int i = 0; i < 8; i++) {
        int tt = (1 + i < len) ? (1 + i) : (len - 1);   // clamped (garbage ok)
        fbuf[i] = fb[(size_t)tt * KSTATES];
    }

    const int s8 = steps & ~7;
    for (int t0 = 0; t0 < s8; t0 += 8) {
#pragma unroll
        for (int j = 0; j < 8; j++) {
            float h = __expf(fbuf[j]);                 // MUFU, off-path
            float b0;
            float s = crf_dot_hybrid2(Msc, Mp2, eaddr, e, b0);
            if ((j & 3) == 0)                          // renorm every 4 steps
                h *= crf_renorm_b0(b0, off);
            e = s * h;
            crf_store_hi(eaddr, lane, e);
            int tt = 9 + t0 + j;                       // clamped refill slot j
            tt = (tt < len) ? tt : (len - 1);
            fbuf[j] = fb[(size_t)tt * KSTATES];
        }
    }
    for (int t = s8; t < steps; t++) {                 // <=7 step tail
        float h = __expf(fbuf[t - s8]);
        float b0;
        float s = crf_dot_hybrid2(Msc, Mp2, eaddr, e, b0);
        h *= crf_renorm_b0(b0, off);
        e = s * h;
        crf_store_hi(eaddr, lane, e);
    }

    // forward_score = off*ln2 + log( (expM @ e)[STOP] ); pending renorm in off
    {
        float b0;
        float sfin  = crf_dot_hybrid2(Msc, Mp2, eaddr, e, b0);
        float sstop = __shfl_sync(FULLMASK, sfin, STOP_IDX);
        if (lane == 0)
            g_fwd[b] = (float)off * LN2 + __logf(sstop);
    }

    // ---- fused mean: last block reduces (fwd - gold) deterministically ----
    unsigned lastflag = 0;
    if (lane == 0) {
        __threadfence();
        unsigned old = atomicAdd(&g_count, 1u);
        lastflag = (old == gridDim.x - 1) ? 1u : 0u;
    }
    lastflag = __shfl_sync(FULLMASK, lastflag, 0);
    if (lastflag) {
        __threadfence();
        float v = 0.0f;
        for (int i = lane; i < B; i += 32)       // fixed order -> deterministic
            v += g_fwd[i] - g_gold[i];
#pragma unroll
        for (int d = 16; d; d >>= 1)
            v += __shfl_xor_sync(FULLMASK, v, d);
        if (lane == 0) {
            out[0] = v / (float)B;
            g_count = 0;                         // reset for next graph replay
        }
    }
}

// Gold score: embarrassingly parallel. One warp per batch, lanes stride t.
__global__ void __launch_bounds__(128)
crf_gold_kernel(const float* __restrict__ feats,
                const float* __restrict__ trans,
                const int*   __restrict__ tags,
                const int*   __restrict__ lens,
                int B, int T)
{
    __shared__ float sh_trans[KSTATES * KSTATES];
    const int tid  = threadIdx.x;
    const int wid  = tid >> 5;
    const int lane = tid & 31;

    for (int i = tid; i < KSTATES * KSTATES; i += 128)
        sh_trans[i] = trans[i];
    __syncthreads();

    const int b = blockIdx.x * 4 + wid;
    if (b >= B) return;

    const int* tb = tags + (size_t)b * T;
    const float* fbase = feats + (size_t)b * T * KSTATES;
    const int len = lens[b];

    float g = 0.0f;
    for (int t = lane; t < len; t += 32) {
        int tg    = tb[t];
        int tprev = (t == 0) ? START_IDX : tb[t - 1];
        g += fbase[(size_t)t * KSTATES + tg] + sh_trans[tg * KSTATES + tprev];
    }
#pragma unroll
    for (int d = 16; d; d >>= 1)
        g += __shfl_xor_sync(FULLMASK, g, d);
    if (lane == 0)
        g_gold[b] = g + sh_trans[STOP_IDX * KSTATES + tb[len - 1]];
}

extern "C" void kernel_launch(void* const* d_in, const int* in_sizes, int n_in,
                              void* d_out, int out_size)
{
    const float* feats = (const float*)d_in[0];   // [B,T,K] f32
    const float* trans = (const float*)d_in[1];   // [K,K]   f32
    const int*   tags  = (const int*)  d_in[2];   // [B,T]   i32
    const int*   lens  = (const int*)  d_in[3];   // [B]     i32

    int B = in_sizes[3];
    int T = in_sizes[2] / B;

    crf_gold_kernel<<<(B + 3) / 4, 128>>>(feats, trans, tags, lens, B, T);
    crf_forward_kernel<<<B, 32>>>(feats, trans, lens, (float*)d_out, B, T);
}

// round 16
// speedup vs baseline: 5.2063x; 2.4012x over previous
#include <cuda_runtime.h>
#include <cstdint>

// CRF loss: mean_b( logZ_b - gold_b )
// KEY IDEA (this round): the forward recurrence e_t = diag(h_t) M e_{t-1}
// is a product of POSITIVE matrices -> Hilbert-metric contraction makes the
// direction of e_t forget its start geometrically fast. So each sequence is
// split into chunks of CHUNK steps; each chunk warp runs WARM warm-up steps
// from a uniform vector (converges onto the true direction), then its real
// steps, accumulating only the telescoping log-magnitude gain
//   delta_c = off*ln2 + log nu(e_out) - log nu(e_in),   nu(x) = sum_n x[n]
// Chunk 0 starts exactly from the true init; the chunk containing t=len ends
// with the STOP-row dot instead of nu. Sum of deltas = logZ (error ~1e-30
// per boundary for random transitions). Wall: 2047 serial steps -> 352.
// Step body = the proven smem-exchange path (1 STS + 8 LDS.128 + 15 f32x2
// FMA; renorm every 4 steps via shfl, exact in integer 'off').

#define KSTATES   32
#define START_IDX 30
#define STOP_IDX  31
#define FULLMASK  0xffffffffu
#define LN2       0.6931471805599453f
#define CHUNK     256
#define WARM      96

__device__ float    g_chunk[8192];    // per-(batch,chunk) contributions
__device__ float    g_gold[4096];     // per-batch gold scores
__device__ unsigned g_count;          // zero-init; reset by last block

// s[lane] = sum_{p=0..29} expM[lane][p] * e[p], e gathered from smem.
// (p=30: e[START]=0 for t>=1 and warm-start; p=31: column STOP of M is 0.)
__device__ __forceinline__ float crf_dot_smem(const unsigned long long* __restrict__ Mp,
                                              unsigned eaddr)
{
    unsigned long long ev[16];
#pragma unroll
    for (int q = 0; q < 8; q++) {
        asm volatile("ld.shared.v2.u64 {%0,%1}, [%2];"
                     : "=l"(ev[2 * q]), "=l"(ev[2 * q + 1])
                     : "r"(eaddr + 16u * q));
    }
    unsigned long long a0 = 0ull, a1 = 0ull, a2 = 0ull, a3 = 0ull;
#pragma unroll
    for (int i = 0; i < 12; i += 4) {
        asm("fma.rn.f32x2 %0, %1, %2, %0;" : "+l"(a0) : "l"(Mp[i    ]), "l"(ev[i    ]));
        asm("fma.rn.f32x2 %0, %1, %2, %0;" : "+l"(a1) : "l"(Mp[i + 1]), "l"(ev[i + 1]));
        asm("fma.rn.f32x2 %0, %1, %2, %0;" : "+l"(a2) : "l"(Mp[i + 2]), "l"(ev[i + 2]));
        asm("fma.rn.f32x2 %0, %1, %2, %0;" : "+l"(a3) : "l"(Mp[i + 3]), "l"(ev[i + 3]));
    }
    asm("fma.rn.f32x2 %0, %1, %2, %0;" : "+l"(a0) : "l"(Mp[12]), "l"(ev[12]));
    asm("fma.rn.f32x2 %0, %1, %2, %0;" : "+l"(a1) : "l"(Mp[13]), "l"(ev[13]));
    asm("fma.rn.f32x2 %0, %1, %2, %0;" : "+l"(a2) : "l"(Mp[14]), "l"(ev[14]));

    unsigned long long s01, s2;
    asm("add.rn.f32x2 %0, %1, %2;" : "=l"(s01) : "l"(a0),  "l"(a1));
    asm("add.rn.f32x2 %0, %1, %2;" : "=l"(s2)  : "l"(a2),  "l"(s01));
    asm("add.rn.f32x2 %0, %1, %2;" : "=l"(s2)  : "l"(a3),  "l"(s2));
    float lo, hi;
    asm("mov.b64 {%0, %1}, %2;" : "=f"(lo), "=f"(hi) : "l"(s2));
    return lo + hi;
}

__device__ __forceinline__ void crf_store_e(unsigned eaddr, int lane, float e)
{
    asm volatile("st.shared.f32 [%0], %1;"
                 :: "r"(eaddr + 4u * (unsigned)lane), "f"(e));
}

// 2^-k from e[0]'s exponent (register copy via shfl), k accumulated into off.
__device__ __forceinline__ float crf_renorm(float e, int& off)
{
    float c  = __shfl_sync(FULLMASK, e, 0);
    int   ie = (int)((__float_as_uint(c) >> 23) & 0xFF);
    ie = (ie == 0) ? 127 : ie;
    off += ie - 127;
    return __uint_as_float((unsigned)(254 - ie) << 23);
}

// Run `count` recurrence steps for times tbase..tbase+count-1.
// Prefetch clamped to lenm1 (valid memory; clamped values unused).
__device__ __forceinline__ void crf_run(const unsigned long long* __restrict__ Mp,
                                        unsigned eaddr, int lane,
                                        const float* __restrict__ fb,
                                        int tbase, int count, int lenm1,
                                        float& e, int& off)
{
    float fbuf[8];
#pragma unroll
    for (int i = 0; i < 8; i++) {
        int tt = tbase + i; tt = (tt < lenm1) ? tt : lenm1;
        fbuf[i] = fb[(size_t)tt * KSTATES];
    }
    const int s8 = count & ~7;
    for (int q = 0; q < s8; q += 8) {
#pragma unroll
        for (int j = 0; j < 8; j++) {
            float h = __expf(fbuf[j]);             // MUFU, off-path
            if ((j & 3) == 0)                      // renorm every 4 steps
                h *= crf_renorm(e, off);
            float s = crf_dot_smem(Mp, eaddr);
            e = s * h;
            crf_store_e(eaddr, lane, e);
            int tt = tbase + q + 8 + j; tt = (tt < lenm1) ? tt : lenm1;
            fbuf[j] = fb[(size_t)tt * KSTATES];
        }
    }
    for (int s = s8; s < count; s++) {             // <=7 step tail
        float h = __expf(fbuf[s - s8]) * crf_renorm(e, off);
        float sv = crf_dot_smem(Mp, eaddr);
        e = sv * h;
        crf_store_e(eaddr, lane, e);
    }
}

__device__ __forceinline__ float warp_sum(float v)
{
#pragma unroll
    for (int d = 16; d; d >>= 1)
        v += __shfl_xor_sync(FULLMASK, v, d);
    return v;
}

__global__ void __launch_bounds__(128)
crf_kernel(const float* __restrict__ feats,
           const float* __restrict__ trans,
           const int*   __restrict__ tags,
           const int*   __restrict__ lens,
           float* __restrict__ out,
           int B, int T, int nch, int nfwd_blocks)
{
    __shared__ __align__(16) float sh_e[4][KSTATES];
    const int tid  = threadIdx.x;
    const int wid  = tid >> 5;
    const int lane = tid & 31;

    if ((int)blockIdx.x < nfwd_blocks) {
        // ================= FORWARD CHUNKS =================
        const int id = blockIdx.x * 4 + wid;        // (batch, chunk) flat id
        if (id < B * nch) {
            const int b   = id / nch;
            const int c   = id % nch;
            const int len = lens[b];
            const int t0  = c * CHUNK;

            if (c > 0 && t0 >= len) {
                if (lane == 0) g_chunk[id] = 0.0f;   // inactive chunk
            } else {
                const unsigned eaddr =
                    (unsigned)__cvta_generic_to_shared(&sh_e[wid][0]);

                // Packed expM row: Mp[q] = (expM[lane][2q], expM[lane][2q+1]).
                // exp(-10000) -> exactly 0 (row START, column STOP).
                unsigned long long Mp[15];
#pragma unroll
                for (int q = 0; q < 15; q++) {
                    float m0 = __expf(trans[lane * KSTATES + 2 * q]);
                    float m1 = __expf(trans[lane * KSTATES + 2 * q + 1]);
                    asm("mov.b64 %0, {%1, %2};" : "=l"(Mp[q]) : "f"(m0), "f"(m1));
                }

                const float* fb = feats + (size_t)b * T * KSTATES + lane;
                const int E     = (t0 + CHUNK < len) ? (t0 + CHUNK) : len;
                const int lenm1 = len - 1;

                float e;
                int   off = 0;
                float nu_in_log;

                if (c == 0) {
                    // exact init: t=0 peeled
                    e = __expf(trans[lane * KSTATES + START_IDX] + fb[0]);
                    crf_store_e(eaddr, lane, e);
                    nu_in_log = 0.0f;
                    crf_run(Mp, eaddr, lane, fb, 1, E - 1, lenm1, e, off);
                } else {
                    // warm-up from uniform direction (Hilbert contraction)
                    e = (lane < 30) ? 1.0f : 0.0f;
                    crf_store_e(eaddr, lane, e);
                    crf_run(Mp, eaddr, lane, fb, t0 - WARM, WARM, lenm1, e, off);
                    nu_in_log = __logf(warp_sum(e));
                    off = 0;
                    crf_run(Mp, eaddr, lane, fb, t0, E - t0, lenm1, e, off);
                }

                float endlog;
                if (E == len) {
                    // final: log( exp(trans[STOP,:]) . e )  (lane 31 = STOP row)
                    float sfin  = crf_dot_smem(Mp, eaddr);
                    float sstop = __shfl_sync(FULLMASK, sfin, STOP_IDX);
                    endlog = __logf(sstop);
                } else {
                    endlog = __logf(warp_sum(e));
                }
                if (lane == 0)
                    g_chunk[id] = (float)off * LN2 + endlog - nu_in_log;
            }
        }
    } else {
        // ================= GOLD SCORE =================
        const int b = (blockIdx.x - nfwd_blocks) * 4 + wid;
        if (b < B) {
            const int* tb = tags + (size_t)b * T;
            const float* fbase = feats + (size_t)b * T * KSTATES;
            const int len = lens[b];
            float g = 0.0f;
            for (int t = lane; t < len; t += 32) {
                int tg    = tb[t];
                int tprev = (t == 0) ? START_IDX : tb[t - 1];
                g += fbase[(size_t)t * KSTATES + tg] + trans[tg * KSTATES + tprev];
            }
            g = warp_sum(g);
            if (lane == 0)
                g_gold[b] = g + trans[STOP_IDX * KSTATES + tb[len - 1]];
        }
    }

    // ---- fused mean: last block reduces everything deterministically ----
    __shared__ unsigned sh_last;
    __syncthreads();
    if (tid == 0) {
        __threadfence();
        unsigned old = atomicAdd(&g_count, 1u);
        sh_last = (old == gridDim.x - 1) ? 1u : 0u;
    }
    __syncthreads();
    if (sh_last && wid == 0) {
        __threadfence();
        float v = 0.0f;
        for (int i = lane; i < B * nch; i += 32)   // fixed order -> deterministic
            v += g_chunk[i];
        for (int i = lane; i < B; i += 32)
            v -= g_gold[i];
        v = warp_sum(v);
        if (lane == 0) {
            out[0] = v / (float)B;
            g_count = 0;                           // reset for next graph replay
        }
    }
}

extern "C" void kernel_launch(void* const* d_in, const int* in_sizes, int n_in,
                              void* d_out, int out_size)
{
    const float* feats = (const float*)d_in[0];   // [B,T,K] f32
    const float* trans = (const float*)d_in[1];   // [K,K]   f32
    const int*   tags  = (const int*)  d_in[2];   // [B,T]   i32
    const int*   lens  = (const int*)  d_in[3];   // [B]     i32

    int B = in_sizes[3];
    int T = in_sizes[2] / B;

    int nch  = (T + CHUNK - 1) / CHUNK;           // chunks per sequence
    int nfwd = (B * nch + 3) / 4;                 // 4 chunk-warps per block
    int ngold = (B + 3) / 4;

    crf_kernel<<<nfwd + ngold, 128>>>(feats, trans, tags, lens,
                                      (float*)d_out, B, T, nch, nfwd);
}